// round 14
// baseline (speedup 1.0000x reference)
#include <cuda_runtime.h>
#include <cuda_fp16.h>
#include <math.h>

#define NN   50000
#define FIN  256
#define HID  64
#define CC   40
#define EE   1600000

#define NC        (NN*CC)
#define OFF_LOGSM 0
#define OFF_XOUT  (NC)
#define OFF_COS   (2*NC)
#define OFF_GNN   (2*NC + EE)
#define OFF_SM    (2*NC + 2*EE)

#define SCAN_T 1024
#define STILE  4096
#define SNB    13            // ceil(50000/4096)

#define FLAG_A (1u << 30)
#define FLAG_P (2u << 30)
#define VALMSK ((1u << 30) - 1u)

typedef unsigned long long ull;
typedef unsigned int uint;

// ---------------- device scratch ----------------
__device__ __half2 g_xwh[NN*32];   // xw fp16 -> scaled in-place to xw' = dinv*xw
__device__ float   g_xn[NN*CC];    // xn fp32 [N,40]
__device__ __half2 g_hwh[NN*20];   // hw' fp16: row = 40 halves = 5 uint4
__device__ float   g_dinv[NN];
__device__ int2    g_adjeid[EE];   // {src, eid} per CSR slot
__device__ int     g_degi[NN];
__device__ int     g_rowptr[NN+1];
__device__ int     g_cursor[NN];
__device__ unsigned g_scanw[SNB];

// ---------------- f32x2 helpers ----------------
__device__ __forceinline__ void fma2(ull& d, ull a, ull b) {
    asm("fma.rn.f32x2 %0, %1, %2, %0;" : "+l"(d) : "l"(a), "l"(b));
}
__device__ __forceinline__ ull pack2(float x) {
    ull r; asm("mov.b64 %0, {%1, %1};" : "=l"(r) : "f"(x)); return r;
}
__device__ __forceinline__ ull mul2(ull a, ull b) {
    ull r; asm("mul.rn.f32x2 %0, %1, %2;" : "=l"(r) : "l"(a), "l"(b)); return r;
}
__device__ __forceinline__ uint h2u(float lo, float hi) {
    __half2 h = __floats2half2_rn(lo, hi);
    return *(uint*)&h;
}
__device__ __forceinline__ float2 u2f(uint u) {
    return __half22float2(*(__half2*)&u);
}

// inline dtype detection: warp 0 of each block checks 64 high words
__device__ __forceinline__ int detect_flag(const unsigned* u, int* sflag) {
    if (threadIdx.x < 32) {
        unsigned v = u[2*threadIdx.x + 1] | u[2*(threadIdx.x + 32) + 1];
        bool nz = __any_sync(0xffffffffu, v != 0u);
        if (threadIdx.x == 0) *sflag = nz ? 0 : 1;   // all-zero high words => int64
    }
    __syncthreads();
    return *sflag;
}

// ---------------- convert: degree count + gnn_edge output ----------------
__global__ void k_convert(const void* __restrict__ p,
                          const float* __restrict__ ew,
                          float* __restrict__ out) {
    __shared__ int sflag;
    int flag = detect_flag((const unsigned*)p, &sflag);
    int e = blockIdx.x * blockDim.x + threadIdx.x;
    if (e >= EE) return;
    int d;
    if (flag) d = (int)((const long long*)p)[e + EE];
    else      d = ((const int*)p)[e + EE];
    atomicAdd(&g_degi[d], 1);
    out[OFF_GNN + e] = (ew[e] > 0.5f) ? 1.0f : -1.0f;
}

// ---------------- single-pass scan, 4 items/thread, 13 blocks ------------
__global__ void __launch_bounds__(SCAN_T) k_scan() {
    __shared__ int wsum[32];
    __shared__ int blockpfx;
    int tid = threadIdx.x, b = blockIdx.x;
    int base = b * STILE + tid * 4;
    int lane = tid & 31, wid = tid >> 5;
    int4 d = make_int4(0, 0, 0, 0);
    if (base < NN) d = ((const int4*)g_degi)[base >> 2];
    int tsum = d.x + d.y + d.z + d.w;
    int s = tsum;
    #pragma unroll
    for (int o = 1; o < 32; o <<= 1) {
        int t2 = __shfl_up_sync(0xffffffffu, s, o);
        if (lane >= o) s += t2;
    }
    if (lane == 31) wsum[wid] = s;
    __syncthreads();
    if (wid == 0) {
        int w = wsum[lane];
        #pragma unroll
        for (int o = 1; o < 32; o <<= 1) {
            int t2 = __shfl_up_sync(0xffffffffu, w, o);
            if (lane >= o) w += t2;
        }
        wsum[lane] = w;
    }
    __syncthreads();
    int inc = s + (wid ? wsum[wid - 1] : 0);

    if (tid == SCAN_T - 1) {
        unsigned agg = (unsigned)inc;
        if (b == 0) {
            g_scanw[0] = FLAG_P | agg;
            blockpfx = 0;
        } else {
            g_scanw[b] = FLAG_A | agg;
            int run = 0, idx = b - 1;
            while (true) {
                unsigned w;
                do { w = *(volatile unsigned*)&g_scanw[idx]; } while (w == 0u);
                run += (int)(w & VALMSK);
                if (w & FLAG_P) break;
                idx--;
            }
            g_scanw[b] = FLAG_P | (unsigned)(run + inc);
            blockpfx = run;
        }
    }
    __syncthreads();
    if (base < NN) {
        int p = blockpfx + inc - tsum;
        int r0 = p + d.x, r1 = r0 + d.y, r2 = r1 + d.z, r3 = r2 + d.w;
        g_rowptr[base + 1] = r0;
        g_rowptr[base + 2] = r1;
        g_rowptr[base + 3] = r2;
        g_rowptr[base + 4] = r3;
        ((int4*)g_cursor)[base >> 2] = make_int4(p, r0, r1, r2);
        ((float4*)g_dinv)[base >> 2] = make_float4(
            rsqrtf((float)(d.x + 1)), rsqrtf((float)(d.y + 1)),
            rsqrtf((float)(d.z + 1)), rsqrtf((float)(d.w + 1)));
        if (base == 0) g_rowptr[0] = 0;
    }
}

// ---------------- fill CSR: {src, eid} int2 per slot ----------------------
__global__ void k_fill(const void* __restrict__ p) {
    __shared__ int sflag;
    int flag = detect_flag((const unsigned*)p, &sflag);
    int e = blockIdx.x * blockDim.x + threadIdx.x;
    if (e >= EE) return;
    int s, d;
    if (flag) {
        const long long* q = (const long long*)p;
        s = (int)q[e]; d = (int)q[e + EE];
    } else {
        const int* q = (const int*)p;
        s = q[e]; d = q[e + EE];
    }
    int pos = atomicAdd(&g_cursor[d], 1);
    g_adjeid[pos] = make_int2(s, e);
}

// ---------------- GEMM1: xwh[N,64] = fp16(x[N,256] @ W1[256,64]) ----------
// R11 config (proven 53.7us): 128 threads, tile 128x64, microtile 8x8,
// in-register A duplication via pack2
#define G1_ROWS 128
union F4U { float4 f; ull u[2]; };
__global__ void __launch_bounds__(128) k_gemm1(const float* __restrict__ x,
                                               const float* __restrict__ W) {
    __shared__ float Xs[16][G1_ROWS + 4];    // [k][row] plain floats
    __shared__ float Ws[16][68];             // [k][col] plain floats
    int t = threadIdx.x;          // 128
    int rowBase = blockIdx.x * G1_ROWS;
    int tr = t >> 3;              // 0..15  (8 rows each)
    int tc = t & 7;               // 0..7   (8 cols each = 4 ull pairs)
    ull acc[8][4];
    #pragma unroll
    for (int r = 0; r < 8; r++)
        #pragma unroll
        for (int c = 0; c < 4; c++) acc[r][c] = 0ULL;

    for (int kb = 0; kb < 16; kb++) {
        // Xs fill: thread t owns row t (16 k-values, plain)
        {
            int gr = rowBase + t;
            #pragma unroll
            for (int q = 0; q < 4; q++) {
                float4 v = (gr < NN) ? *(const float4*)&x[gr * FIN + kb * 16 + q * 4]
                                     : make_float4(0.f, 0.f, 0.f, 0.f);
                Xs[q*4+0][t] = v.x;
                Xs[q*4+1][t] = v.y;
                Xs[q*4+2][t] = v.z;
                Xs[q*4+3][t] = v.w;
            }
        }
        // Ws fill: 16 k-rows x 64 floats = 256 float4 ; 128 threads x 2
        #pragma unroll
        for (int q = 0; q < 2; q++) {
            int L = t + q * 128;             // 0..255
            int kk = L >> 4, p4 = L & 15;
            float4 w = *(const float4*)&W[(kb * 16 + kk) * HID + p4 * 4];
            *(float4*)&Ws[kk][p4 * 4] = w;
        }
        __syncthreads();
        #pragma unroll
        for (int kk = 0; kk < 16; kk++) {
            float4 af0 = *(const float4*)&Xs[kk][tr * 8];
            float4 af1 = *(const float4*)&Xs[kk][tr * 8 + 4];
            ull a[8];
            a[0] = pack2(af0.x); a[1] = pack2(af0.y);
            a[2] = pack2(af0.z); a[3] = pack2(af0.w);
            a[4] = pack2(af1.x); a[5] = pack2(af1.y);
            a[6] = pack2(af1.z); a[7] = pack2(af1.w);
            F4U b0, b1;
            b0.f = *(const float4*)&Ws[kk][tc * 8];
            b1.f = *(const float4*)&Ws[kk][tc * 8 + 4];
            ull b[4] = {b0.u[0], b0.u[1], b1.u[0], b1.u[1]};
            #pragma unroll
            for (int r = 0; r < 8; r++)
                #pragma unroll
                for (int c = 0; c < 4; c++) fma2(acc[r][c], a[r], b[c]);
        }
        __syncthreads();
    }
    #pragma unroll
    for (int r = 0; r < 8; r++) {
        int row = rowBase + tr * 8 + r;
        if (row < NN) {
            uint u[4];
            #pragma unroll
            for (int c = 0; c < 4; c++) {
                float2 f = *(float2*)&acc[r][c];
                u[c] = h2u(f.x, f.y);
            }
            *(uint4*)&g_xwh[row * 32 + tc * 4] = make_uint4(u[0], u[1], u[2], u[3]);
        }
    }
}

// ---------------- scale: xw' = dinv[row] * xw (in place, fp32 math) -------
__global__ void k_scale() {
    int tid = blockIdx.x * blockDim.x + threadIdx.x;   // NN*8
    if (tid >= NN * 8) return;
    int row = tid >> 3;
    float di = g_dinv[row];
    uint4 v = ((uint4*)g_xwh)[tid];
    float2 f;
    f = u2f(v.x); v.x = h2u(f.x * di, f.y * di);
    f = u2f(v.y); v.y = h2u(f.x * di, f.y * di);
    f = u2f(v.z); v.z = h2u(f.x * di, f.y * di);
    f = u2f(v.w); v.w = h2u(f.x * di, f.y * di);
    ((uint4*)g_xwh)[tid] = v;
}

// ---------------- gather1 FUSED with GEMM2 --------------------------------
// h = relu(di*(Σ xw'[s] + xw'[i]) + b1) stays in regs/smem fp32;
// hw' = fp16(di * (h @ W2)) written directly.
__global__ void __launch_bounds__(256) k_gather1f(const float* __restrict__ b1,
                                                  const float* __restrict__ W2) {
    __shared__ ull  W2p[64][21];     // col-pairs, padded
    __shared__ float h_sm[8][68];    // 8 warps x 64 floats (+pad)
    int t = threadIdx.x;
    // load W2 pairs: 64 x 20 = 1280 ull ; 256 threads x 5
    #pragma unroll
    for (int q = 0; q < 5; q++) {
        int L = t + q * 256;          // 0..1279
        int k = L / 20, j = L - k * 20;
        W2p[k][j] = *(const ull*)&W2[k * 40 + j * 2];
    }
    __syncthreads();

    int warp = t >> 5, lane = t & 31;
    int i = blockIdx.x * 8 + warp;    // grid*8 == NN exactly
    int start = g_rowptr[i], end = g_rowptr[i + 1];
    int fl = lane & 7, es = lane >> 3;     // es 0..3
    const uint4* X = (const uint4*)g_xwh;  // row = 8 uint4
    float a[8], c[8];
    #pragma unroll
    for (int k = 0; k < 8; k++) { a[k] = 0.f; c[k] = 0.f; }
    for (int b = start + es; b < end; b += 8) {
        {
            int s = g_adjeid[b].x;
            uint4 v = X[s * 8 + fl];
            float2 f;
            f = u2f(v.x); a[0] += f.x; a[1] += f.y;
            f = u2f(v.y); a[2] += f.x; a[3] += f.y;
            f = u2f(v.z); a[4] += f.x; a[5] += f.y;
            f = u2f(v.w); a[6] += f.x; a[7] += f.y;
        }
        int b2 = b + 4;
        if (b2 < end) {
            int s = g_adjeid[b2].x;
            uint4 v = X[s * 8 + fl];
            float2 f;
            f = u2f(v.x); c[0] += f.x; c[1] += f.y;
            f = u2f(v.y); c[2] += f.x; c[3] += f.y;
            f = u2f(v.z); c[4] += f.x; c[5] += f.y;
            f = u2f(v.w); c[6] += f.x; c[7] += f.y;
        }
    }
    #pragma unroll
    for (int k = 0; k < 8; k++) a[k] += c[k];
    #pragma unroll
    for (int k = 0; k < 8; k++) a[k] += __shfl_down_sync(0xffffffffu, a[k], 16);
    #pragma unroll
    for (int k = 0; k < 8; k++) a[k] += __shfl_down_sync(0xffffffffu, a[k], 8);
    float di = g_dinv[i];
    if (lane < 8) {
        uint4 sv = X[i * 8 + fl];
        float sf[8];
        float2 f;
        f = u2f(sv.x); sf[0] = f.x; sf[1] = f.y;
        f = u2f(sv.y); sf[2] = f.x; sf[3] = f.y;
        f = u2f(sv.z); sf[4] = f.x; sf[5] = f.y;
        f = u2f(sv.w); sf[6] = f.x; sf[7] = f.y;
        float4 bb0 = ((const float4*)b1)[fl * 2];
        float4 bb1 = ((const float4*)b1)[fl * 2 + 1];
        float bbv[8] = {bb0.x, bb0.y, bb0.z, bb0.w, bb1.x, bb1.y, bb1.z, bb1.w};
        float* hrow = &h_sm[warp][fl * 8];
        #pragma unroll
        for (int k = 0; k < 8; k++)
            hrow[k] = fmaxf(di * (a[k] + sf[k]) + bbv[k], 0.f);
    }
    __syncwarp();
    // GEMM2 for this row: lanes 0..19 each produce one col-pair
    if (lane < 20) {
        ull acc = 0ULL;
        const float4* h4 = (const float4*)h_sm[warp];
        #pragma unroll
        for (int kq = 0; kq < 16; kq++) {
            float4 hv = h4[kq];
            fma2(acc, pack2(hv.x), W2p[kq*4+0][lane]);
            fma2(acc, pack2(hv.y), W2p[kq*4+1][lane]);
            fma2(acc, pack2(hv.z), W2p[kq*4+2][lane]);
            fma2(acc, pack2(hv.w), W2p[kq*4+3][lane]);
        }
        ull m = mul2(acc, pack2(di));
        float2 f = *(float2*)&m;
        ((uint*)g_hwh)[i * 20 + lane] = h2u(f.x, f.y);
    }
}

// ---------------- layer-2 gather fused with rowfinal ----------------------
// writes log_softmax/x_out/softmax to out; xn (fp32) -> g_xn
__global__ void k_gather2f(const float* __restrict__ b2, float* __restrict__ out) {
    int warp = threadIdx.x >> 5, lane = threadIdx.x & 31;
    int i = blockIdx.x * 8 + warp;
    if (i >= NN) return;
    int start = g_rowptr[i], end = g_rowptr[i + 1];
    int es = lane / 10;
    int fl = lane - es * 10;
    bool act = (lane < 30);
    const uint2* H = (const uint2*)g_hwh;   // row = 10 uint2
    float4 a0 = make_float4(0.f,0.f,0.f,0.f), a1 = a0;
    if (act) {
        for (int b = start + es; b < end; b += 6) {
            {
                int s = g_adjeid[b].x;
                uint2 hv = H[s * 10 + fl];
                float2 f0 = u2f(hv.x), f1 = u2f(hv.y);
                a0.x += f0.x; a0.y += f0.y; a0.z += f1.x; a0.w += f1.y;
            }
            int b2i = b + 3;
            if (b2i < end) {
                int s = g_adjeid[b2i].x;
                uint2 hv = H[s * 10 + fl];
                float2 f0 = u2f(hv.x), f1 = u2f(hv.y);
                a1.x += f0.x; a1.y += f0.y; a1.z += f1.x; a1.w += f1.y;
            }
        }
    }
    a0.x += a1.x; a0.y += a1.y; a0.z += a1.z; a0.w += a1.w;
    a0.x += __shfl_down_sync(0xffffffffu, a0.x, 10) + __shfl_down_sync(0xffffffffu, a0.x, 20);
    a0.y += __shfl_down_sync(0xffffffffu, a0.y, 10) + __shfl_down_sync(0xffffffffu, a0.y, 20);
    a0.z += __shfl_down_sync(0xffffffffu, a0.z, 10) + __shfl_down_sync(0xffffffffu, a0.z, 20);
    a0.w += __shfl_down_sync(0xffffffffu, a0.w, 10) + __shfl_down_sync(0xffffffffu, a0.w, 20);

    const float NEG = -1e30f;
    float4 v = make_float4(NEG, NEG, NEG, NEG);
    if (lane < 10) {
        uint2 sv = H[i * 10 + fl];
        float2 s0 = u2f(sv.x), s1 = u2f(sv.y);
        float di = g_dinv[i];
        float4 bb = ((const float4*)b2)[fl];
        v.x = di * (a0.x + s0.x) + bb.x;
        v.y = di * (a0.y + s0.y) + bb.y;
        v.z = di * (a0.z + s1.x) + bb.z;
        v.w = di * (a0.w + s1.y) + bb.w;
    }
    float m = fmaxf(fmaxf(v.x, v.y), fmaxf(v.z, v.w));
    #pragma unroll
    for (int o = 16; o > 0; o >>= 1) m = fmaxf(m, __shfl_xor_sync(0xffffffffu, m, o));
    float4 ev = make_float4(0.f, 0.f, 0.f, 0.f);
    float s = 0.f, ss = 0.f;
    if (lane < 10) {
        ev.x = __expf(v.x - m); ev.y = __expf(v.y - m);
        ev.z = __expf(v.z - m); ev.w = __expf(v.w - m);
        s  = ev.x + ev.y + ev.z + ev.w;
        ss = v.x*v.x + v.y*v.y + v.z*v.z + v.w*v.w;
    }
    #pragma unroll
    for (int o = 16; o > 0; o >>= 1) {
        s  += __shfl_xor_sync(0xffffffffu, s, o);
        ss += __shfl_xor_sync(0xffffffffu, ss, o);
    }
    if (lane < 10) {
        float lse = m + logf(s);
        float inv_s = 1.0f / s;
        float rn = 1.0f / fmaxf(sqrtf(ss), 1e-8f);
        int idx = i * 10 + fl;
        ((float4*)(out + OFF_XOUT))[idx] = v;
        ((float4*)(out + OFF_LOGSM))[idx] = make_float4(v.x - lse, v.y - lse, v.z - lse, v.w - lse);
        ((float4*)(out + OFF_SM))[idx] = make_float4(ev.x * inv_s, ev.y * inv_s, ev.z * inv_s, ev.w * inv_s);
        ((float4*)g_xn)[idx] = make_float4(v.x * rn, v.y * rn, v.z * rn, v.w * rn);
    }
}

// ---------------- per-edge cosine via CSR (d-row register reuse, fp32) ----
__global__ void k_edge(float* __restrict__ out) {
    int warp = threadIdx.x >> 5, lane = threadIdx.x & 31;
    int row = blockIdx.x * 8 + warp;
    if (row >= NN) return;
    int start = g_rowptr[row], end = g_rowptr[row + 1];
    const float4* XN = (const float4*)g_xn;   // row = 10 float4
    float4 nd[10];
    #pragma unroll
    for (int j = 0; j < 10; j++) nd[j] = XN[row * 10 + j];
    for (int slot = start + lane; slot < end; slot += 32) {
        int2 ae = g_adjeid[slot];
        int s = ae.x;
        float d0 = 0.f, d1 = 0.f, d2 = 0.f, d3 = 0.f;
        #pragma unroll
        for (int j = 0; j < 10; j += 2) {
            float4 a = XN[s * 10 + j];
            float4 b = XN[s * 10 + j + 1];
            d0 += a.x * nd[j].x + a.y * nd[j].y;
            d1 += a.z * nd[j].z + a.w * nd[j].w;
            d2 += b.x * nd[j+1].x + b.y * nd[j+1].y;
            d3 += b.z * nd[j+1].z + b.w * nd[j+1].w;
        }
        out[OFF_COS + ae.y] = 1.0f - (d0 + d1 + d2 + d3);
    }
}

// ---------------- launch ----------------
extern "C" void kernel_launch(void* const* d_in, const int* in_sizes, int n_in,
                              void* d_out, int out_size) {
    const float* x   = (const float*)d_in[0];
    const void*  ei  = d_in[1];
    const float* ew  = (const float*)d_in[2];
    const float* W1  = (const float*)d_in[3];
    const float* b1  = (const float*)d_in[4];
    const float* W2  = (const float*)d_in[5];
    const float* b2  = (const float*)d_in[6];
    float* out = (float*)d_out;

    const int TB = 256;

    static cudaStream_t s2 = nullptr;
    static cudaEvent_t ev0 = nullptr, evS = nullptr, ev1 = nullptr;
    static void* p_degi = nullptr;
    static void* p_scanw = nullptr;
    if (!s2) {
        cudaStreamCreateWithFlags(&s2, cudaStreamNonBlocking);
        cudaEventCreateWithFlags(&ev0, cudaEventDisableTiming);
        cudaEventCreateWithFlags(&evS, cudaEventDisableTiming);
        cudaEventCreateWithFlags(&ev1, cudaEventDisableTiming);
        cudaGetSymbolAddress(&p_degi, g_degi);
        cudaGetSymbolAddress(&p_scanw, g_scanw);
    }

    // fork point for the independent GEMM1 branch (executes from t=0)
    cudaEventRecord(ev0, 0);
    cudaStreamWaitEvent(s2, ev0, 0);

    // edge-structure chain (memsets are graph memset nodes, not kernels)
    cudaMemsetAsync(p_degi, 0, NN * sizeof(int), 0);
    cudaMemsetAsync(p_scanw, 0, SNB * sizeof(unsigned), 0);
    k_convert<<<(EE + TB - 1) / TB, TB>>>(ei, ew, out);               // launch 0
    k_scan<<<SNB, SCAN_T>>>();                                        // launch 1
    cudaEventRecord(evS, 0);
    k_fill<<<(EE + TB - 1) / TB, TB>>>(ei);                           // launch 2

    // side stream: gemm1 from t=0, then dinv pre-scale (needs scan)
    k_gemm1<<<(NN + G1_ROWS - 1) / G1_ROWS, 128, 0, s2>>>(x, W1);     // launch 3 <- profiled
    cudaStreamWaitEvent(s2, evS, 0);
    k_scale<<<(NN * 8 + TB - 1) / TB, TB, 0, s2>>>();                 // launch 4
    cudaEventRecord(ev1, s2);
    cudaStreamWaitEvent(0, ev1, 0);

    // join: fused gather1+gemm2, then tail
    k_gather1f<<<NN / 8, 256>>>(b1, W2);                              // launch 5
    k_gather2f<<<(NN + 7) / 8, 256>>>(b2, out);                       // launch 6
    k_edge<<<(NN + 7) / 8, 256>>>(out);                               // launch 7
}

// round 15
// speedup vs baseline: 1.1736x; 1.1736x over previous
#include <cuda_runtime.h>
#include <cuda_fp16.h>
#include <math.h>

#define NN   50000
#define FIN  256
#define HID  64
#define CC   40
#define EE   1600000

#define NC        (NN*CC)
#define OFF_LOGSM 0
#define OFF_XOUT  (NC)
#define OFF_COS   (2*NC)
#define OFF_GNN   (2*NC + EE)
#define OFF_SM    (2*NC + 2*EE)

#define SCAN_T 1024
#define STILE  4096
#define SNB    13            // ceil(50000/4096)

#define FLAG_A (1u << 30)
#define FLAG_P (2u << 30)
#define VALMSK ((1u << 30) - 1u)

typedef unsigned long long ull;
typedef unsigned int uint;

// ---------------- device scratch ----------------
__device__ __half2 g_xwh[NN*32];   // xw fp16 -> scaled in-place to xw' = dinv*xw
__device__ float   g_xn[NN*CC];    // xn fp32 [N,40]
__device__ __half2 g_hwh[NN*20];   // hw' fp16: row = 40 halves = 5 uint4
__device__ float   g_dinv[NN];
__device__ int2    g_adjeid[EE];   // {src, eid} per CSR slot
__device__ int     g_degi[NN];
__device__ int     g_rowptr[NN+1];
__device__ int     g_cursor[NN];
__device__ unsigned g_scanw[SNB];

// ---------------- f32x2 helpers ----------------
__device__ __forceinline__ void fma2(ull& d, ull a, ull b) {
    asm("fma.rn.f32x2 %0, %1, %2, %0;" : "+l"(d) : "l"(a), "l"(b));
}
__device__ __forceinline__ ull pack2(float x) {
    ull r; asm("mov.b64 %0, {%1, %1};" : "=l"(r) : "f"(x)); return r;
}
__device__ __forceinline__ ull mul2(ull a, ull b) {
    ull r; asm("mul.rn.f32x2 %0, %1, %2;" : "=l"(r) : "l"(a), "l"(b)); return r;
}
__device__ __forceinline__ uint h2u(float lo, float hi) {
    __half2 h = __floats2half2_rn(lo, hi);
    return *(uint*)&h;
}
__device__ __forceinline__ float2 u2f(uint u) {
    return __half22float2(*(__half2*)&u);
}

// inline dtype detection: warp 0 of each block checks 64 high words
__device__ __forceinline__ int detect_flag(const unsigned* u, int* sflag) {
    if (threadIdx.x < 32) {
        unsigned v = u[2*threadIdx.x + 1] | u[2*(threadIdx.x + 32) + 1];
        bool nz = __any_sync(0xffffffffu, v != 0u);
        if (threadIdx.x == 0) *sflag = nz ? 0 : 1;   // all-zero high words => int64
    }
    __syncthreads();
    return *sflag;
}

// ---------------- convert: degree count + gnn_edge output ----------------
__global__ void k_convert(const void* __restrict__ p,
                          const float* __restrict__ ew,
                          float* __restrict__ out) {
    __shared__ int sflag;
    int flag = detect_flag((const unsigned*)p, &sflag);
    int e = blockIdx.x * blockDim.x + threadIdx.x;
    if (e >= EE) return;
    int d;
    if (flag) d = (int)((const long long*)p)[e + EE];
    else      d = ((const int*)p)[e + EE];
    atomicAdd(&g_degi[d], 1);
    out[OFF_GNN + e] = (ew[e] > 0.5f) ? 1.0f : -1.0f;
}

// ---------------- single-pass scan, 4 items/thread, 13 blocks ------------
__global__ void __launch_bounds__(SCAN_T) k_scan() {
    __shared__ int wsum[32];
    __shared__ int blockpfx;
    int tid = threadIdx.x, b = blockIdx.x;
    int base = b * STILE + tid * 4;
    int lane = tid & 31, wid = tid >> 5;
    int4 d = make_int4(0, 0, 0, 0);
    if (base < NN) d = ((const int4*)g_degi)[base >> 2];
    int tsum = d.x + d.y + d.z + d.w;
    int s = tsum;
    #pragma unroll
    for (int o = 1; o < 32; o <<= 1) {
        int t2 = __shfl_up_sync(0xffffffffu, s, o);
        if (lane >= o) s += t2;
    }
    if (lane == 31) wsum[wid] = s;
    __syncthreads();
    if (wid == 0) {
        int w = wsum[lane];
        #pragma unroll
        for (int o = 1; o < 32; o <<= 1) {
            int t2 = __shfl_up_sync(0xffffffffu, w, o);
            if (lane >= o) w += t2;
        }
        wsum[lane] = w;
    }
    __syncthreads();
    int inc = s + (wid ? wsum[wid - 1] : 0);

    if (tid == SCAN_T - 1) {
        unsigned agg = (unsigned)inc;
        if (b == 0) {
            g_scanw[0] = FLAG_P | agg;
            blockpfx = 0;
        } else {
            g_scanw[b] = FLAG_A | agg;
            int run = 0, idx = b - 1;
            while (true) {
                unsigned w;
                do { w = *(volatile unsigned*)&g_scanw[idx]; } while (w == 0u);
                run += (int)(w & VALMSK);
                if (w & FLAG_P) break;
                idx--;
            }
            g_scanw[b] = FLAG_P | (unsigned)(run + inc);
            blockpfx = run;
        }
    }
    __syncthreads();
    if (base < NN) {
        int p = blockpfx + inc - tsum;
        int r0 = p + d.x, r1 = r0 + d.y, r2 = r1 + d.z, r3 = r2 + d.w;
        g_rowptr[base + 1] = r0;
        g_rowptr[base + 2] = r1;
        g_rowptr[base + 3] = r2;
        g_rowptr[base + 4] = r3;
        ((int4*)g_cursor)[base >> 2] = make_int4(p, r0, r1, r2);
        ((float4*)g_dinv)[base >> 2] = make_float4(
            rsqrtf((float)(d.x + 1)), rsqrtf((float)(d.y + 1)),
            rsqrtf((float)(d.z + 1)), rsqrtf((float)(d.w + 1)));
        if (base == 0) g_rowptr[0] = 0;
    }
}

// ---------------- fill CSR: {src, eid} int2 per slot ----------------------
__global__ void k_fill(const void* __restrict__ p) {
    __shared__ int sflag;
    int flag = detect_flag((const unsigned*)p, &sflag);
    int e = blockIdx.x * blockDim.x + threadIdx.x;
    if (e >= EE) return;
    int s, d;
    if (flag) {
        const long long* q = (const long long*)p;
        s = (int)q[e]; d = (int)q[e + EE];
    } else {
        const int* q = (const int*)p;
        s = q[e]; d = q[e + EE];
    }
    int pos = atomicAdd(&g_cursor[d], 1);
    g_adjeid[pos] = make_int2(s, e);
}

// ---------------- GEMM1: xwh[N,64] = fp16(x[N,256] @ W1[256,64]) ----------
// R11 config (53.7us at normal clocks): 128 threads, tile 128x64,
// microtile 8x8, in-register A duplication via pack2
#define G1_ROWS 128
union F4U { float4 f; ull u[2]; };
__global__ void __launch_bounds__(128) k_gemm1(const float* __restrict__ x,
                                               const float* __restrict__ W) {
    __shared__ float Xs[16][G1_ROWS + 4];    // [k][row] plain floats
    __shared__ float Ws[16][68];             // [k][col] plain floats
    int t = threadIdx.x;          // 128
    int rowBase = blockIdx.x * G1_ROWS;
    int tr = t >> 3;              // 0..15  (8 rows each)
    int tc = t & 7;               // 0..7   (8 cols each = 4 ull pairs)
    ull acc[8][4];
    #pragma unroll
    for (int r = 0; r < 8; r++)
        #pragma unroll
        for (int c = 0; c < 4; c++) acc[r][c] = 0ULL;

    for (int kb = 0; kb < 16; kb++) {
        {
            int gr = rowBase + t;
            #pragma unroll
            for (int q = 0; q < 4; q++) {
                float4 v = (gr < NN) ? *(const float4*)&x[gr * FIN + kb * 16 + q * 4]
                                     : make_float4(0.f, 0.f, 0.f, 0.f);
                Xs[q*4+0][t] = v.x;
                Xs[q*4+1][t] = v.y;
                Xs[q*4+2][t] = v.z;
                Xs[q*4+3][t] = v.w;
            }
        }
        #pragma unroll
        for (int q = 0; q < 2; q++) {
            int L = t + q * 128;             // 0..255
            int kk = L >> 4, p4 = L & 15;
            float4 w = *(const float4*)&W[(kb * 16 + kk) * HID + p4 * 4];
            *(float4*)&Ws[kk][p4 * 4] = w;
        }
        __syncthreads();
        #pragma unroll
        for (int kk = 0; kk < 16; kk++) {
            float4 af0 = *(const float4*)&Xs[kk][tr * 8];
            float4 af1 = *(const float4*)&Xs[kk][tr * 8 + 4];
            ull a[8];
            a[0] = pack2(af0.x); a[1] = pack2(af0.y);
            a[2] = pack2(af0.z); a[3] = pack2(af0.w);
            a[4] = pack2(af1.x); a[5] = pack2(af1.y);
            a[6] = pack2(af1.z); a[7] = pack2(af1.w);
            F4U b0, b1;
            b0.f = *(const float4*)&Ws[kk][tc * 8];
            b1.f = *(const float4*)&Ws[kk][tc * 8 + 4];
            ull b[4] = {b0.u[0], b0.u[1], b1.u[0], b1.u[1]};
            #pragma unroll
            for (int r = 0; r < 8; r++)
                #pragma unroll
                for (int c = 0; c < 4; c++) fma2(acc[r][c], a[r], b[c]);
        }
        __syncthreads();
    }
    #pragma unroll
    for (int r = 0; r < 8; r++) {
        int row = rowBase + tr * 8 + r;
        if (row < NN) {
            uint u[4];
            #pragma unroll
            for (int c = 0; c < 4; c++) {
                float2 f = *(float2*)&acc[r][c];
                u[c] = h2u(f.x, f.y);
            }
            *(uint4*)&g_xwh[row * 32 + tc * 4] = make_uint4(u[0], u[1], u[2], u[3]);
        }
    }
}

// ---------------- scale: xw' = dinv[row] * xw (in place, fp32 math) -------
__global__ void k_scale() {
    int tid = blockIdx.x * blockDim.x + threadIdx.x;   // NN*8
    if (tid >= NN * 8) return;
    int row = tid >> 3;
    float di = g_dinv[row];
    uint4 v = ((uint4*)g_xwh)[tid];
    float2 f;
    f = u2f(v.x); v.x = h2u(f.x * di, f.y * di);
    f = u2f(v.y); v.y = h2u(f.x * di, f.y * di);
    f = u2f(v.z); v.z = h2u(f.x * di, f.y * di);
    f = u2f(v.w); v.w = h2u(f.x * di, f.y * di);
    ((uint4*)g_xwh)[tid] = v;
}

// ---------------- gather1 FUSED with GEMM2 --------------------------------
// h = relu(di*(Σ xw'[s] + xw'[i]) + b1) stays in regs/smem fp32;
// hw' = fp16(di * (h @ W2)) written directly.
__global__ void __launch_bounds__(256) k_gather1f(const float* __restrict__ b1,
                                                  const float* __restrict__ W2) {
    __shared__ ull  W2p[64][21];     // col-pairs, padded
    __shared__ float h_sm[8][68];    // 8 warps x 64 floats (+pad)
    int t = threadIdx.x;
    #pragma unroll
    for (int q = 0; q < 5; q++) {
        int L = t + q * 256;          // 0..1279
        int k = L / 20, j = L - k * 20;
        W2p[k][j] = *(const ull*)&W2[k * 40 + j * 2];
    }
    __syncthreads();

    int warp = t >> 5, lane = t & 31;
    int i = blockIdx.x * 8 + warp;    // grid*8 == NN exactly
    int start = g_rowptr[i], end = g_rowptr[i + 1];
    int fl = lane & 7, es = lane >> 3;     // es 0..3
    const uint4* X = (const uint4*)g_xwh;  // row = 8 uint4
    float a[8], c[8];
    #pragma unroll
    for (int k = 0; k < 8; k++) { a[k] = 0.f; c[k] = 0.f; }
    for (int b = start + es; b < end; b += 8) {
        {
            int s = g_adjeid[b].x;
            uint4 v = X[s * 8 + fl];
            float2 f;
            f = u2f(v.x); a[0] += f.x; a[1] += f.y;
            f = u2f(v.y); a[2] += f.x; a[3] += f.y;
            f = u2f(v.z); a[4] += f.x; a[5] += f.y;
            f = u2f(v.w); a[6] += f.x; a[7] += f.y;
        }
        int b2 = b + 4;
        if (b2 < end) {
            int s = g_adjeid[b2].x;
            uint4 v = X[s * 8 + fl];
            float2 f;
            f = u2f(v.x); c[0] += f.x; c[1] += f.y;
            f = u2f(v.y); c[2] += f.x; c[3] += f.y;
            f = u2f(v.z); c[4] += f.x; c[5] += f.y;
            f = u2f(v.w); c[6] += f.x; c[7] += f.y;
        }
    }
    #pragma unroll
    for (int k = 0; k < 8; k++) a[k] += c[k];
    #pragma unroll
    for (int k = 0; k < 8; k++) a[k] += __shfl_down_sync(0xffffffffu, a[k], 16);
    #pragma unroll
    for (int k = 0; k < 8; k++) a[k] += __shfl_down_sync(0xffffffffu, a[k], 8);
    float di = g_dinv[i];
    if (lane < 8) {
        uint4 sv = X[i * 8 + fl];
        float sf[8];
        float2 f;
        f = u2f(sv.x); sf[0] = f.x; sf[1] = f.y;
        f = u2f(sv.y); sf[2] = f.x; sf[3] = f.y;
        f = u2f(sv.z); sf[4] = f.x; sf[5] = f.y;
        f = u2f(sv.w); sf[6] = f.x; sf[7] = f.y;
        float4 bb0 = ((const float4*)b1)[fl * 2];
        float4 bb1 = ((const float4*)b1)[fl * 2 + 1];
        float bbv[8] = {bb0.x, bb0.y, bb0.z, bb0.w, bb1.x, bb1.y, bb1.z, bb1.w};
        float* hrow = &h_sm[warp][fl * 8];
        #pragma unroll
        for (int k = 0; k < 8; k++)
            hrow[k] = fmaxf(di * (a[k] + sf[k]) + bbv[k], 0.f);
    }
    __syncwarp();
    // GEMM2 for this row: lanes 0..19 each produce one col-pair
    if (lane < 20) {
        ull acc = 0ULL;
        const float4* h4 = (const float4*)h_sm[warp];
        #pragma unroll
        for (int kq = 0; kq < 16; kq++) {
            float4 hv = h4[kq];
            fma2(acc, pack2(hv.x), W2p[kq*4+0][lane]);
            fma2(acc, pack2(hv.y), W2p[kq*4+1][lane]);
            fma2(acc, pack2(hv.z), W2p[kq*4+2][lane]);
            fma2(acc, pack2(hv.w), W2p[kq*4+3][lane]);
        }
        ull m = mul2(acc, pack2(di));
        float2 f = *(float2*)&m;
        ((uint*)g_hwh)[i * 20 + lane] = h2u(f.x, f.y);
    }
}

// ---------------- layer-2 gather fused with rowfinal ----------------------
// writes log_softmax/x_out/softmax to out; xn (fp32) -> g_xn
__global__ void k_gather2f(const float* __restrict__ b2, float* __restrict__ out) {
    int warp = threadIdx.x >> 5, lane = threadIdx.x & 31;
    int i = blockIdx.x * 8 + warp;
    if (i >= NN) return;
    int start = g_rowptr[i], end = g_rowptr[i + 1];
    int es = lane / 10;
    int fl = lane - es * 10;
    bool act = (lane < 30);
    const uint2* H = (const uint2*)g_hwh;   // row = 10 uint2
    float4 a0 = make_float4(0.f,0.f,0.f,0.f), a1 = a0;
    if (act) {
        for (int b = start + es; b < end; b += 6) {
            {
                int s = g_adjeid[b].x;
                uint2 hv = H[s * 10 + fl];
                float2 f0 = u2f(hv.x), f1 = u2f(hv.y);
                a0.x += f0.x; a0.y += f0.y; a0.z += f1.x; a0.w += f1.y;
            }
            int b2i = b + 3;
            if (b2i < end) {
                int s = g_adjeid[b2i].x;
                uint2 hv = H[s * 10 + fl];
                float2 f0 = u2f(hv.x), f1 = u2f(hv.y);
                a1.x += f0.x; a1.y += f0.y; a1.z += f1.x; a1.w += f1.y;
            }
        }
    }
    a0.x += a1.x; a0.y += a1.y; a0.z += a1.z; a0.w += a1.w;
    a0.x += __shfl_down_sync(0xffffffffu, a0.x, 10) + __shfl_down_sync(0xffffffffu, a0.x, 20);
    a0.y += __shfl_down_sync(0xffffffffu, a0.y, 10) + __shfl_down_sync(0xffffffffu, a0.y, 20);
    a0.z += __shfl_down_sync(0xffffffffu, a0.z, 10) + __shfl_down_sync(0xffffffffu, a0.z, 20);
    a0.w += __shfl_down_sync(0xffffffffu, a0.w, 10) + __shfl_down_sync(0xffffffffu, a0.w, 20);

    const float NEG = -1e30f;
    float4 v = make_float4(NEG, NEG, NEG, NEG);
    if (lane < 10) {
        uint2 sv = H[i * 10 + fl];
        float2 s0 = u2f(sv.x), s1 = u2f(sv.y);
        float di = g_dinv[i];
        float4 bb = ((const float4*)b2)[fl];
        v.x = di * (a0.x + s0.x) + bb.x;
        v.y = di * (a0.y + s0.y) + bb.y;
        v.z = di * (a0.z + s1.x) + bb.z;
        v.w = di * (a0.w + s1.y) + bb.w;
    }
    float m = fmaxf(fmaxf(v.x, v.y), fmaxf(v.z, v.w));
    #pragma unroll
    for (int o = 16; o > 0; o >>= 1) m = fmaxf(m, __shfl_xor_sync(0xffffffffu, m, o));
    float4 ev = make_float4(0.f, 0.f, 0.f, 0.f);
    float s = 0.f, ss = 0.f;
    if (lane < 10) {
        ev.x = __expf(v.x - m); ev.y = __expf(v.y - m);
        ev.z = __expf(v.z - m); ev.w = __expf(v.w - m);
        s  = ev.x + ev.y + ev.z + ev.w;
        ss = v.x*v.x + v.y*v.y + v.z*v.z + v.w*v.w;
    }
    #pragma unroll
    for (int o = 16; o > 0; o >>= 1) {
        s  += __shfl_xor_sync(0xffffffffu, s, o);
        ss += __shfl_xor_sync(0xffffffffu, ss, o);
    }
    if (lane < 10) {
        float lse = m + logf(s);
        float inv_s = 1.0f / s;
        float rn = 1.0f / fmaxf(sqrtf(ss), 1e-8f);
        int idx = i * 10 + fl;
        ((float4*)(out + OFF_XOUT))[idx] = v;
        ((float4*)(out + OFF_LOGSM))[idx] = make_float4(v.x - lse, v.y - lse, v.z - lse, v.w - lse);
        ((float4*)(out + OFF_SM))[idx] = make_float4(ev.x * inv_s, ev.y * inv_s, ev.z * inv_s, ev.w * inv_s);
        ((float4*)g_xn)[idx] = make_float4(v.x * rn, v.y * rn, v.z * rn, v.w * rn);
    }
}

// ---------------- per-edge cosine via CSR (d-row register reuse, fp32) ----
__global__ void k_edge(float* __restrict__ out) {
    int warp = threadIdx.x >> 5, lane = threadIdx.x & 31;
    int row = blockIdx.x * 8 + warp;
    if (row >= NN) return;
    int start = g_rowptr[row], end = g_rowptr[row + 1];
    const float4* XN = (const float4*)g_xn;   // row = 10 float4
    float4 nd[10];
    #pragma unroll
    for (int j = 0; j < 10; j++) nd[j] = XN[row * 10 + j];
    for (int slot = start + lane; slot < end; slot += 32) {
        int2 ae = g_adjeid[slot];
        int s = ae.x;
        float d0 = 0.f, d1 = 0.f, d2 = 0.f, d3 = 0.f;
        #pragma unroll
        for (int j = 0; j < 10; j += 2) {
            float4 a = XN[s * 10 + j];
            float4 b = XN[s * 10 + j + 1];
            d0 += a.x * nd[j].x + a.y * nd[j].y;
            d1 += a.z * nd[j].z + a.w * nd[j].w;
            d2 += b.x * nd[j+1].x + b.y * nd[j+1].y;
            d3 += b.z * nd[j+1].z + b.w * nd[j+1].w;
        }
        out[OFF_COS + ae.y] = 1.0f - (d0 + d1 + d2 + d3);
    }
}

// ---------------- launch ----------------
extern "C" void kernel_launch(void* const* d_in, const int* in_sizes, int n_in,
                              void* d_out, int out_size) {
    const float* x   = (const float*)d_in[0];
    const void*  ei  = d_in[1];
    const float* ew  = (const float*)d_in[2];
    const float* W1  = (const float*)d_in[3];
    const float* b1  = (const float*)d_in[4];
    const float* W2  = (const float*)d_in[5];
    const float* b2  = (const float*)d_in[6];
    float* out = (float*)d_out;

    const int TB = 256;

    static cudaStream_t s2 = nullptr;
    static cudaEvent_t ev0 = nullptr, evS = nullptr, ev1 = nullptr;
    static void* p_degi = nullptr;
    static void* p_scanw = nullptr;
    if (!s2) {
        cudaStreamCreateWithFlags(&s2, cudaStreamNonBlocking);
        cudaEventCreateWithFlags(&ev0, cudaEventDisableTiming);
        cudaEventCreateWithFlags(&evS, cudaEventDisableTiming);
        cudaEventCreateWithFlags(&ev1, cudaEventDisableTiming);
        cudaGetSymbolAddress(&p_degi, g_degi);
        cudaGetSymbolAddress(&p_scanw, g_scanw);
    }

    // fork point for the independent GEMM1 branch (executes from t=0)
    cudaEventRecord(ev0, 0);
    cudaStreamWaitEvent(s2, ev0, 0);

    // edge-structure chain (memsets are graph memset nodes, not kernels)
    cudaMemsetAsync(p_degi, 0, NN * sizeof(int), 0);
    cudaMemsetAsync(p_scanw, 0, SNB * sizeof(unsigned), 0);
    k_convert<<<(EE + TB - 1) / TB, TB>>>(ei, ew, out);               // launch 0
    k_scan<<<SNB, SCAN_T>>>();                                        // launch 1
    cudaEventRecord(evS, 0);
    k_fill<<<(EE + TB - 1) / TB, TB>>>(ei);                           // launch 2

    // side stream: gemm1 from t=0, then dinv pre-scale (needs scan)
    k_gemm1<<<(NN + G1_ROWS - 1) / G1_ROWS, 128, 0, s2>>>(x, W1);     // launch 3 <- profiled
    cudaStreamWaitEvent(s2, evS, 0);
    k_scale<<<(NN * 8 + TB - 1) / TB, TB, 0, s2>>>();                 // launch 4
    cudaEventRecord(ev1, s2);
    cudaStreamWaitEvent(0, ev1, 0);

    // join: fused gather1+gemm2, then tail
    k_gather1f<<<NN / 8, 256>>>(b1, W2);                              // launch 5
    k_gather2f<<<(NN + 7) / 8, 256>>>(b2, out);                       // launch 6
    k_edge<<<(NN + 7) / 8, 256>>>(out);                               // launch 7
}

// round 16
// speedup vs baseline: 1.4417x; 1.2284x over previous
#include <cuda_runtime.h>
#include <cuda_fp16.h>
#include <math.h>

#define NN   50000
#define FIN  256
#define HID  64
#define CC   40
#define EE   1600000

#define NC        (NN*CC)
#define OFF_LOGSM 0
#define OFF_XOUT  (NC)
#define OFF_COS   (2*NC)
#define OFF_GNN   (2*NC + EE)
#define OFF_SM    (2*NC + 2*EE)

#define SCAN_T 1024
#define STILE  4096
#define SNB    13            // ceil(50000/4096)

#define FLAG_A (1u << 30)
#define FLAG_P (2u << 30)
#define VALMSK ((1u << 30) - 1u)

typedef unsigned long long ull;
typedef unsigned int uint;

// ---------------- device scratch ----------------
__device__ __half2 g_xwh[NN*32];   // xw fp16 (raw, unscaled): row = 64 halves
__device__ float   g_xn[NN*CC];    // xn fp32 [N,40]
__device__ __half2 g_hwh[NN*20];   // hw' fp16: row = 40 halves
__device__ float   g_dinv[NN];
__device__ int2    g_adjeid[EE];   // {src, eid} per CSR slot
__device__ int     g_degi[NN];
__device__ int     g_rowptr[NN+1];
__device__ int     g_cursor[NN];
__device__ unsigned g_scanw[SNB];

// ---------------- f32x2 helpers ----------------
__device__ __forceinline__ void fma2(ull& d, ull a, ull b) {
    asm("fma.rn.f32x2 %0, %1, %2, %0;" : "+l"(d) : "l"(a), "l"(b));
}
__device__ __forceinline__ ull pack2(float x) {
    ull r; asm("mov.b64 %0, {%1, %1};" : "=l"(r) : "f"(x)); return r;
}
__device__ __forceinline__ ull mul2(ull a, ull b) {
    ull r; asm("mul.rn.f32x2 %0, %1, %2;" : "=l"(r) : "l"(a), "l"(b)); return r;
}
__device__ __forceinline__ uint h2u(float lo, float hi) {
    __half2 h = __floats2half2_rn(lo, hi);
    return *(uint*)&h;
}
__device__ __forceinline__ float2 u2f(uint u) {
    return __half22float2(*(__half2*)&u);
}

// inline dtype detection: warp 0 of each block checks 64 high words
__device__ __forceinline__ int detect_flag(const unsigned* u, int* sflag) {
    if (threadIdx.x < 32) {
        unsigned v = u[2*threadIdx.x + 1] | u[2*(threadIdx.x + 32) + 1];
        bool nz = __any_sync(0xffffffffu, v != 0u);
        if (threadIdx.x == 0) *sflag = nz ? 0 : 1;   // all-zero high words => int64
    }
    __syncthreads();
    return *sflag;
}

// ---------------- convert: degree count + gnn_edge + scanw zero ----------
__global__ void k_convert(const void* __restrict__ p,
                          const float* __restrict__ ew,
                          float* __restrict__ out) {
    __shared__ int sflag;
    int flag = detect_flag((const unsigned*)p, &sflag);
    int e = blockIdx.x * blockDim.x + threadIdx.x;
    if (blockIdx.x == 0 && threadIdx.x < SNB) g_scanw[threadIdx.x] = 0u;
    if (e >= EE) return;
    int d;
    if (flag) d = (int)((const long long*)p)[e + EE];
    else      d = ((const int*)p)[e + EE];
    atomicAdd(&g_degi[d], 1);
    out[OFF_GNN + e] = (ew[e] > 0.5f) ? 1.0f : -1.0f;
}

// ---------------- single-pass scan, 4 items/thread, 13 blocks ------------
__global__ void __launch_bounds__(SCAN_T) k_scan() {
    __shared__ int wsum[32];
    __shared__ int blockpfx;
    int tid = threadIdx.x, b = blockIdx.x;
    int base = b * STILE + tid * 4;
    int lane = tid & 31, wid = tid >> 5;
    int4 d = make_int4(0, 0, 0, 0);
    if (base < NN) d = ((const int4*)g_degi)[base >> 2];
    int tsum = d.x + d.y + d.z + d.w;
    int s = tsum;
    #pragma unroll
    for (int o = 1; o < 32; o <<= 1) {
        int t2 = __shfl_up_sync(0xffffffffu, s, o);
        if (lane >= o) s += t2;
    }
    if (lane == 31) wsum[wid] = s;
    __syncthreads();
    if (wid == 0) {
        int w = wsum[lane];
        #pragma unroll
        for (int o = 1; o < 32; o <<= 1) {
            int t2 = __shfl_up_sync(0xffffffffu, w, o);
            if (lane >= o) w += t2;
        }
        wsum[lane] = w;
    }
    __syncthreads();
    int inc = s + (wid ? wsum[wid - 1] : 0);

    if (tid == SCAN_T - 1) {
        unsigned agg = (unsigned)inc;
        if (b == 0) {
            g_scanw[0] = FLAG_P | agg;
            blockpfx = 0;
        } else {
            g_scanw[b] = FLAG_A | agg;
            int run = 0, idx = b - 1;
            while (true) {
                unsigned w;
                do { w = *(volatile unsigned*)&g_scanw[idx]; } while (w == 0u);
                run += (int)(w & VALMSK);
                if (w & FLAG_P) break;
                idx--;
            }
            g_scanw[b] = FLAG_P | (unsigned)(run + inc);
            blockpfx = run;
        }
    }
    __syncthreads();
    if (base < NN) {
        int p = blockpfx + inc - tsum;
        int r0 = p + d.x, r1 = r0 + d.y, r2 = r1 + d.z, r3 = r2 + d.w;
        g_rowptr[base + 1] = r0;
        g_rowptr[base + 2] = r1;
        g_rowptr[base + 3] = r2;
        g_rowptr[base + 4] = r3;
        ((int4*)g_cursor)[base >> 2] = make_int4(p, r0, r1, r2);
        ((float4*)g_dinv)[base >> 2] = make_float4(
            rsqrtf((float)(d.x + 1)), rsqrtf((float)(d.y + 1)),
            rsqrtf((float)(d.z + 1)), rsqrtf((float)(d.w + 1)));
        if (base == 0) g_rowptr[0] = 0;
    }
}

// ---------------- fill CSR: {src, eid} int2 per slot ----------------------
__global__ void k_fill(const void* __restrict__ p) {
    __shared__ int sflag;
    int flag = detect_flag((const unsigned*)p, &sflag);
    int e = blockIdx.x * blockDim.x + threadIdx.x;
    if (e >= EE) return;
    int s, d;
    if (flag) {
        const long long* q = (const long long*)p;
        s = (int)q[e]; d = (int)q[e + EE];
    } else {
        const int* q = (const int*)p;
        s = q[e]; d = q[e + EE];
    }
    int pos = atomicAdd(&g_cursor[d], 1);
    g_adjeid[pos] = make_int2(s, e);
}

// ---------------- GEMM1: xwh[N,64] = fp16(x[N,256] @ W1[256,64]) ----------
// proven config: 128 threads, tile 128x64, microtile 8x4 ull, in-reg A dup
#define G1_ROWS 128
union F4U { float4 f; ull u[2]; };
__global__ void __launch_bounds__(128) k_gemm1(const float* __restrict__ x,
                                               const float* __restrict__ W) {
    __shared__ float Xs[16][G1_ROWS + 4];
    __shared__ float Ws[16][68];
    int t = threadIdx.x;          // 128
    int rowBase = blockIdx.x * G1_ROWS;
    int tr = t >> 3;              // 0..15  (8 rows each)
    int tc = t & 7;               // 0..7   (8 cols each = 4 ull pairs)
    ull acc[8][4];
    #pragma unroll
    for (int r = 0; r < 8; r++)
        #pragma unroll
        for (int c = 0; c < 4; c++) acc[r][c] = 0ULL;

    for (int kb = 0; kb < 16; kb++) {
        {
            int gr = rowBase + t;
            #pragma unroll
            for (int q = 0; q < 4; q++) {
                float4 v = (gr < NN) ? *(const float4*)&x[gr * FIN + kb * 16 + q * 4]
                                     : make_float4(0.f, 0.f, 0.f, 0.f);
                Xs[q*4+0][t] = v.x;
                Xs[q*4+1][t] = v.y;
                Xs[q*4+2][t] = v.z;
                Xs[q*4+3][t] = v.w;
            }
        }
        #pragma unroll
        for (int q = 0; q < 2; q++) {
            int L = t + q * 128;
            int kk = L >> 4, p4 = L & 15;
            float4 w = *(const float4*)&W[(kb * 16 + kk) * HID + p4 * 4];
            *(float4*)&Ws[kk][p4 * 4] = w;
        }
        __syncthreads();
        #pragma unroll
        for (int kk = 0; kk < 16; kk++) {
            float4 af0 = *(const float4*)&Xs[kk][tr * 8];
            float4 af1 = *(const float4*)&Xs[kk][tr * 8 + 4];
            ull a[8];
            a[0] = pack2(af0.x); a[1] = pack2(af0.y);
            a[2] = pack2(af0.z); a[3] = pack2(af0.w);
            a[4] = pack2(af1.x); a[5] = pack2(af1.y);
            a[6] = pack2(af1.z); a[7] = pack2(af1.w);
            F4U b0, b1;
            b0.f = *(const float4*)&Ws[kk][tc * 8];
            b1.f = *(const float4*)&Ws[kk][tc * 8 + 4];
            ull b[4] = {b0.u[0], b0.u[1], b1.u[0], b1.u[1]};
            #pragma unroll
            for (int r = 0; r < 8; r++)
                #pragma unroll
                for (int c = 0; c < 4; c++) fma2(acc[r][c], a[r], b[c]);
        }
        __syncthreads();
    }
    #pragma unroll
    for (int r = 0; r < 8; r++) {
        int row = rowBase + tr * 8 + r;
        if (row < NN) {
            uint u[4];
            #pragma unroll
            for (int c = 0; c < 4; c++) {
                float2 f = *(float2*)&acc[r][c];
                u[c] = h2u(f.x, f.y);
            }
            *(uint4*)&g_xwh[row * 32 + tc * 4] = make_uint4(u[0], u[1], u[2], u[3]);
        }
    }
}

// ---------------- gather1 FUSED with GEMM2 (dinv[s] in-loop, pipelined) ---
// h = relu(di*(Σ dinv[s]*xw[s] + di*xw[i]) + b1); hw' = fp16(di*(h@W2))
__global__ void __launch_bounds__(256) k_gather1f(const float* __restrict__ b1,
                                                  const float* __restrict__ W2) {
    __shared__ ull  W2p[64][21];     // col-pairs, padded
    __shared__ float h_sm[8][68];    // 8 warps x 64 floats (+pad)
    int t = threadIdx.x;
    #pragma unroll
    for (int q = 0; q < 5; q++) {
        int L = t + q * 256;          // 0..1279
        int k = L / 20, j = L - k * 20;
        W2p[k][j] = *(const ull*)&W2[k * 40 + j * 2];
    }
    __syncthreads();

    int warp = t >> 5, lane = t & 31;
    int i = blockIdx.x * 8 + warp;    // grid*8 == NN exactly
    int start = g_rowptr[i], end = g_rowptr[i + 1];
    int fl = lane & 7, es = lane >> 3;     // es 0..3
    const uint4* X = (const uint4*)g_xwh;  // row = 8 uint4
    float a[8], c[8];
    #pragma unroll
    for (int k = 0; k < 8; k++) { a[k] = 0.f; c[k] = 0.f; }

    // software-pipelined: prefetch next iteration's slots before consuming
    int b0 = start + es;
    int sA = (b0 < end)     ? g_adjeid[b0].x     : -1;
    int sB = (b0 + 4 < end) ? g_adjeid[b0 + 4].x : -1;
    for (int b = b0; b < end; b += 8) {
        int nA = (b + 8 < end)  ? g_adjeid[b + 8].x  : -1;
        int nB = (b + 12 < end) ? g_adjeid[b + 12].x : -1;
        if (sA >= 0) {
            float w = g_dinv[sA];
            uint4 v = X[sA * 8 + fl];
            float2 f;
            f = u2f(v.x); a[0] += f.x * w; a[1] += f.y * w;
            f = u2f(v.y); a[2] += f.x * w; a[3] += f.y * w;
            f = u2f(v.z); a[4] += f.x * w; a[5] += f.y * w;
            f = u2f(v.w); a[6] += f.x * w; a[7] += f.y * w;
        }
        if (sB >= 0) {
            float w = g_dinv[sB];
            uint4 v = X[sB * 8 + fl];
            float2 f;
            f = u2f(v.x); c[0] += f.x * w; c[1] += f.y * w;
            f = u2f(v.y); c[2] += f.x * w; c[3] += f.y * w;
            f = u2f(v.z); c[4] += f.x * w; c[5] += f.y * w;
            f = u2f(v.w); c[6] += f.x * w; c[7] += f.y * w;
        }
        sA = nA; sB = nB;
    }
    #pragma unroll
    for (int k = 0; k < 8; k++) a[k] += c[k];
    #pragma unroll
    for (int k = 0; k < 8; k++) a[k] += __shfl_down_sync(0xffffffffu, a[k], 16);
    #pragma unroll
    for (int k = 0; k < 8; k++) a[k] += __shfl_down_sync(0xffffffffu, a[k], 8);
    float di = g_dinv[i];
    if (lane < 8) {
        uint4 sv = X[i * 8 + fl];
        float sf[8];
        float2 f;
        f = u2f(sv.x); sf[0] = f.x; sf[1] = f.y;
        f = u2f(sv.y); sf[2] = f.x; sf[3] = f.y;
        f = u2f(sv.z); sf[4] = f.x; sf[5] = f.y;
        f = u2f(sv.w); sf[6] = f.x; sf[7] = f.y;
        float4 bb0 = ((const float4*)b1)[fl * 2];
        float4 bb1 = ((const float4*)b1)[fl * 2 + 1];
        float bbv[8] = {bb0.x, bb0.y, bb0.z, bb0.w, bb1.x, bb1.y, bb1.z, bb1.w};
        float* hrow = &h_sm[warp][fl * 8];
        #pragma unroll
        for (int k = 0; k < 8; k++)
            hrow[k] = fmaxf(di * (a[k] + di * sf[k]) + bbv[k], 0.f);
    }
    __syncwarp();
    // GEMM2 for this row: lanes 0..19 each produce one col-pair
    if (lane < 20) {
        ull acc = 0ULL;
        const float4* h4 = (const float4*)h_sm[warp];
        #pragma unroll
        for (int kq = 0; kq < 16; kq++) {
            float4 hv = h4[kq];
            fma2(acc, pack2(hv.x), W2p[kq*4+0][lane]);
            fma2(acc, pack2(hv.y), W2p[kq*4+1][lane]);
            fma2(acc, pack2(hv.z), W2p[kq*4+2][lane]);
            fma2(acc, pack2(hv.w), W2p[kq*4+3][lane]);
        }
        ull m = mul2(acc, pack2(di));
        float2 f = *(float2*)&m;
        ((uint*)g_hwh)[i * 20 + lane] = h2u(f.x, f.y);
    }
}

// ---------------- layer-2 gather fused with rowfinal ----------------------
__global__ void k_gather2f(const float* __restrict__ b2, float* __restrict__ out) {
    int warp = threadIdx.x >> 5, lane = threadIdx.x & 31;
    int i = blockIdx.x * 8 + warp;
    if (i >= NN) return;
    int start = g_rowptr[i], end = g_rowptr[i + 1];
    int es = lane / 10;
    int fl = lane - es * 10;
    bool act = (lane < 30);
    const uint2* H = (const uint2*)g_hwh;   // row = 10 uint2
    float4 a0 = make_float4(0.f,0.f,0.f,0.f), a1 = a0;
    if (act) {
        for (int b = start + es; b < end; b += 6) {
            {
                int s = g_adjeid[b].x;
                uint2 hv = H[s * 10 + fl];
                float2 f0 = u2f(hv.x), f1 = u2f(hv.y);
                a0.x += f0.x; a0.y += f0.y; a0.z += f1.x; a0.w += f1.y;
            }
            int b2i = b + 3;
            if (b2i < end) {
                int s = g_adjeid[b2i].x;
                uint2 hv = H[s * 10 + fl];
                float2 f0 = u2f(hv.x), f1 = u2f(hv.y);
                a1.x += f0.x; a1.y += f0.y; a1.z += f1.x; a1.w += f1.y;
            }
        }
    }
    a0.x += a1.x; a0.y += a1.y; a0.z += a1.z; a0.w += a1.w;
    a0.x += __shfl_down_sync(0xffffffffu, a0.x, 10) + __shfl_down_sync(0xffffffffu, a0.x, 20);
    a0.y += __shfl_down_sync(0xffffffffu, a0.y, 10) + __shfl_down_sync(0xffffffffu, a0.y, 20);
    a0.z += __shfl_down_sync(0xffffffffu, a0.z, 10) + __shfl_down_sync(0xffffffffu, a0.z, 20);
    a0.w += __shfl_down_sync(0xffffffffu, a0.w, 10) + __shfl_down_sync(0xffffffffu, a0.w, 20);

    const float NEG = -1e30f;
    float4 v = make_float4(NEG, NEG, NEG, NEG);
    if (lane < 10) {
        uint2 sv = H[i * 10 + fl];
        float2 s0 = u2f(sv.x), s1 = u2f(sv.y);
        float di = g_dinv[i];
        float4 bb = ((const float4*)b2)[fl];
        v.x = di * (a0.x + s0.x) + bb.x;
        v.y = di * (a0.y + s0.y) + bb.y;
        v.z = di * (a0.z + s1.x) + bb.z;
        v.w = di * (a0.w + s1.y) + bb.w;
    }
    float m = fmaxf(fmaxf(v.x, v.y), fmaxf(v.z, v.w));
    #pragma unroll
    for (int o = 16; o > 0; o >>= 1) m = fmaxf(m, __shfl_xor_sync(0xffffffffu, m, o));
    float4 ev = make_float4(0.f, 0.f, 0.f, 0.f);
    float s = 0.f, ss = 0.f;
    if (lane < 10) {
        ev.x = __expf(v.x - m); ev.y = __expf(v.y - m);
        ev.z = __expf(v.z - m); ev.w = __expf(v.w - m);
        s  = ev.x + ev.y + ev.z + ev.w;
        ss = v.x*v.x + v.y*v.y + v.z*v.z + v.w*v.w;
    }
    #pragma unroll
    for (int o = 16; o > 0; o >>= 1) {
        s  += __shfl_xor_sync(0xffffffffu, s, o);
        ss += __shfl_xor_sync(0xffffffffu, ss, o);
    }
    if (lane < 10) {
        float lse = m + logf(s);
        float inv_s = 1.0f / s;
        float rn = 1.0f / fmaxf(sqrtf(ss), 1e-8f);
        int idx = i * 10 + fl;
        ((float4*)(out + OFF_XOUT))[idx] = v;
        ((float4*)(out + OFF_LOGSM))[idx] = make_float4(v.x - lse, v.y - lse, v.z - lse, v.w - lse);
        ((float4*)(out + OFF_SM))[idx] = make_float4(ev.x * inv_s, ev.y * inv_s, ev.z * inv_s, ev.w * inv_s);
        ((float4*)g_xn)[idx] = make_float4(v.x * rn, v.y * rn, v.z * rn, v.w * rn);
    }
}

// ---------------- per-edge cosine via CSR (d-row register reuse, fp32) ----
__global__ void k_edge(float* __restrict__ out) {
    int warp = threadIdx.x >> 5, lane = threadIdx.x & 31;
    int row = blockIdx.x * 8 + warp;
    if (row >= NN) return;
    int start = g_rowptr[row], end = g_rowptr[row + 1];
    const float4* XN = (const float4*)g_xn;   // row = 10 float4
    float4 nd[10];
    #pragma unroll
    for (int j = 0; j < 10; j++) nd[j] = XN[row * 10 + j];
    for (int slot = start + lane; slot < end; slot += 32) {
        int2 ae = g_adjeid[slot];
        int s = ae.x;
        float d0 = 0.f, d1 = 0.f, d2 = 0.f, d3 = 0.f;
        #pragma unroll
        for (int j = 0; j < 10; j += 2) {
            float4 a = XN[s * 10 + j];
            float4 b = XN[s * 10 + j + 1];
            d0 += a.x * nd[j].x + a.y * nd[j].y;
            d1 += a.z * nd[j].z + a.w * nd[j].w;
            d2 += b.x * nd[j+1].x + b.y * nd[j+1].y;
            d3 += b.z * nd[j+1].z + b.w * nd[j+1].w;
        }
        out[OFF_COS + ae.y] = 1.0f - (d0 + d1 + d2 + d3);
    }
}

// ---------------- launch ----------------
extern "C" void kernel_launch(void* const* d_in, const int* in_sizes, int n_in,
                              void* d_out, int out_size) {
    const float* x   = (const float*)d_in[0];
    const void*  ei  = d_in[1];
    const float* ew  = (const float*)d_in[2];
    const float* W1  = (const float*)d_in[3];
    const float* b1  = (const float*)d_in[4];
    const float* W2  = (const float*)d_in[5];
    const float* b2  = (const float*)d_in[6];
    float* out = (float*)d_out;

    const int TB = 256;

    static cudaStream_t s2 = nullptr;
    static cudaEvent_t ev0 = nullptr, ev1 = nullptr;
    static void* p_degi = nullptr;
    if (!s2) {
        cudaStreamCreateWithFlags(&s2, cudaStreamNonBlocking);
        cudaEventCreateWithFlags(&ev0, cudaEventDisableTiming);
        cudaEventCreateWithFlags(&ev1, cudaEventDisableTiming);
        cudaGetSymbolAddress(&p_degi, g_degi);
    }

    // fork point for the independent GEMM1 branch (executes from t=0)
    cudaEventRecord(ev0, 0);
    cudaStreamWaitEvent(s2, ev0, 0);

    // submission order chosen so node #6 (profiled) = k_gather1f:
    // memset(1) convert(2) scan(3) fill(4) gemm1(5) gather1f(6)
    cudaMemsetAsync(p_degi, 0, NN * sizeof(int), 0);                  // node 1
    k_convert<<<(EE + TB - 1) / TB, TB>>>(ei, ew, out);               // node 2
    k_scan<<<SNB, SCAN_T>>>();                                        // node 3
    k_fill<<<(EE + TB - 1) / TB, TB>>>(ei);                           // node 4

    // side stream: gemm1 from t=0 (raw xw, no dinv dependency)
    k_gemm1<<<(NN + G1_ROWS - 1) / G1_ROWS, 128, 0, s2>>>(x, W1);     // node 5
    cudaEventRecord(ev1, s2);
    cudaStreamWaitEvent(0, ev1, 0);

    // join: fused gather1+gemm2 (dinv applied in-loop), then tail
    k_gather1f<<<NN / 8, 256>>>(b1, W2);                              // node 6 <- profiled
    k_gather2f<<<(NN + 7) / 8, 256>>>(b2, out);                       // node 7
    k_edge<<<(NN + 7) / 8, 256>>>(out);                               // node 8
}

// round 17
// speedup vs baseline: 1.4493x; 1.0053x over previous
#include <cuda_runtime.h>
#include <cuda_fp16.h>
#include <math.h>

#define NN   50000
#define FIN  256
#define HID  64
#define CC   40
#define EE   1600000

#define NC        (NN*CC)
#define OFF_LOGSM 0
#define OFF_XOUT  (NC)
#define OFF_COS   (2*NC)
#define OFF_GNN   (2*NC + EE)
#define OFF_SM    (2*NC + 2*EE)

#define SCAN_T 1024
#define STILE  4096
#define SNB    13            // ceil(50000/4096)

#define FLAG_A (1u << 30)
#define FLAG_P (2u << 30)
#define VALMSK ((1u << 30) - 1u)

typedef unsigned long long ull;
typedef unsigned int uint;

// ---------------- device scratch ----------------
__device__ __half2 g_xwh[NN*32];   // xw fp16 -> scaled in-place to xw' = dinv*xw
__device__ float   g_xn[NN*CC];    // xn fp32 [N,40]
__device__ __half2 g_hwh[NN*20];   // hw' fp16: row = 40 halves
__device__ float   g_dinv[NN];
__device__ int2    g_adjeid[EE];   // {src, eid} per CSR slot
__device__ int     g_degi[NN];
__device__ int     g_rowptr[NN+1];
__device__ int     g_cursor[NN];
__device__ unsigned g_scanw[SNB];

// ---------------- f32x2 helpers ----------------
__device__ __forceinline__ void fma2(ull& d, ull a, ull b) {
    asm("fma.rn.f32x2 %0, %1, %2, %0;" : "+l"(d) : "l"(a), "l"(b));
}
__device__ __forceinline__ ull pack2(float x) {
    ull r; asm("mov.b64 %0, {%1, %1};" : "=l"(r) : "f"(x)); return r;
}
__device__ __forceinline__ ull mul2(ull a, ull b) {
    ull r; asm("mul.rn.f32x2 %0, %1, %2;" : "=l"(r) : "l"(a), "l"(b)); return r;
}
__device__ __forceinline__ uint h2u(float lo, float hi) {
    __half2 h = __floats2half2_rn(lo, hi);
    return *(uint*)&h;
}
__device__ __forceinline__ float2 u2f(uint u) {
    return __half22float2(*(__half2*)&u);
}

// inline dtype detection: warp 0 of each block checks 64 high words
__device__ __forceinline__ int detect_flag(const unsigned* u, int* sflag) {
    if (threadIdx.x < 32) {
        unsigned v = u[2*threadIdx.x + 1] | u[2*(threadIdx.x + 32) + 1];
        bool nz = __any_sync(0xffffffffu, v != 0u);
        if (threadIdx.x == 0) *sflag = nz ? 0 : 1;   // all-zero high words => int64
    }
    __syncthreads();
    return *sflag;
}

// ---------------- convert: degree count + gnn_edge + scanw zero ----------
__global__ void k_convert(const void* __restrict__ p,
                          const float* __restrict__ ew,
                          float* __restrict__ out) {
    __shared__ int sflag;
    int flag = detect_flag((const unsigned*)p, &sflag);
    int e = blockIdx.x * blockDim.x + threadIdx.x;
    if (blockIdx.x == 0 && threadIdx.x < SNB) g_scanw[threadIdx.x] = 0u;
    if (e >= EE) return;
    int d;
    if (flag) d = (int)((const long long*)p)[e + EE];
    else      d = ((const int*)p)[e + EE];
    atomicAdd(&g_degi[d], 1);
    out[OFF_GNN + e] = (ew[e] > 0.5f) ? 1.0f : -1.0f;
}

// ---------------- single-pass scan, 4 items/thread, 13 blocks ------------
__global__ void __launch_bounds__(SCAN_T) k_scan() {
    __shared__ int wsum[32];
    __shared__ int blockpfx;
    int tid = threadIdx.x, b = blockIdx.x;
    int base = b * STILE + tid * 4;
    int lane = tid & 31, wid = tid >> 5;
    int4 d = make_int4(0, 0, 0, 0);
    if (base < NN) d = ((const int4*)g_degi)[base >> 2];
    int tsum = d.x + d.y + d.z + d.w;
    int s = tsum;
    #pragma unroll
    for (int o = 1; o < 32; o <<= 1) {
        int t2 = __shfl_up_sync(0xffffffffu, s, o);
        if (lane >= o) s += t2;
    }
    if (lane == 31) wsum[wid] = s;
    __syncthreads();
    if (wid == 0) {
        int w = wsum[lane];
        #pragma unroll
        for (int o = 1; o < 32; o <<= 1) {
            int t2 = __shfl_up_sync(0xffffffffu, w, o);
            if (lane >= o) w += t2;
        }
        wsum[lane] = w;
    }
    __syncthreads();
    int inc = s + (wid ? wsum[wid - 1] : 0);

    if (tid == SCAN_T - 1) {
        unsigned agg = (unsigned)inc;
        if (b == 0) {
            g_scanw[0] = FLAG_P | agg;
            blockpfx = 0;
        } else {
            g_scanw[b] = FLAG_A | agg;
            int run = 0, idx = b - 1;
            while (true) {
                unsigned w;
                do { w = *(volatile unsigned*)&g_scanw[idx]; } while (w == 0u);
                run += (int)(w & VALMSK);
                if (w & FLAG_P) break;
                idx--;
            }
            g_scanw[b] = FLAG_P | (unsigned)(run + inc);
            blockpfx = run;
        }
    }
    __syncthreads();
    if (base < NN) {
        int p = blockpfx + inc - tsum;
        int r0 = p + d.x, r1 = r0 + d.y, r2 = r1 + d.z, r3 = r2 + d.w;
        g_rowptr[base + 1] = r0;
        g_rowptr[base + 2] = r1;
        g_rowptr[base + 3] = r2;
        g_rowptr[base + 4] = r3;
        ((int4*)g_cursor)[base >> 2] = make_int4(p, r0, r1, r2);
        ((float4*)g_dinv)[base >> 2] = make_float4(
            rsqrtf((float)(d.x + 1)), rsqrtf((float)(d.y + 1)),
            rsqrtf((float)(d.z + 1)), rsqrtf((float)(d.w + 1)));
        if (base == 0) g_rowptr[0] = 0;
    }
}

// ---------------- fill CSR: {src, eid} int2 per slot ----------------------
__global__ void k_fill(const void* __restrict__ p) {
    __shared__ int sflag;
    int flag = detect_flag((const unsigned*)p, &sflag);
    int e = blockIdx.x * blockDim.x + threadIdx.x;
    if (e >= EE) return;
    int s, d;
    if (flag) {
        const long long* q = (const long long*)p;
        s = (int)q[e]; d = (int)q[e + EE];
    } else {
        const int* q = (const int*)p;
        s = q[e]; d = q[e + EE];
    }
    int pos = atomicAdd(&g_cursor[d], 1);
    g_adjeid[pos] = make_int2(s, e);
}

// ---------------- GEMM1: xwh[N,64] = fp16(x[N,256] @ W1[256,64]) ----------
// proven config (53.7us at full clock): 128 threads, tile 128x64,
// microtile 8x8, in-register A duplication via pack2
#define G1_ROWS 128
union F4U { float4 f; ull u[2]; };
__global__ void __launch_bounds__(128) k_gemm1(const float* __restrict__ x,
                                               const float* __restrict__ W) {
    __shared__ float Xs[16][G1_ROWS + 4];
    __shared__ float Ws[16][68];
    int t = threadIdx.x;          // 128
    int rowBase = blockIdx.x * G1_ROWS;
    int tr = t >> 3;              // 0..15  (8 rows each)
    int tc = t & 7;               // 0..7   (8 cols each = 4 ull pairs)
    ull acc[8][4];
    #pragma unroll
    for (int r = 0; r < 8; r++)
        #pragma unroll
        for (int c = 0; c < 4; c++) acc[r][c] = 0ULL;

    for (int kb = 0; kb < 16; kb++) {
        {
            int gr = rowBase + t;
            #pragma unroll
            for (int q = 0; q < 4; q++) {
                float4 v = (gr < NN) ? *(const float4*)&x[gr * FIN + kb * 16 + q * 4]
                                     : make_float4(0.f, 0.f, 0.f, 0.f);
                Xs[q*4+0][t] = v.x;
                Xs[q*4+1][t] = v.y;
                Xs[q*4+2][t] = v.z;
                Xs[q*4+3][t] = v.w;
            }
        }
        #pragma unroll
        for (int q = 0; q < 2; q++) {
            int L = t + q * 128;
            int kk = L >> 4, p4 = L & 15;
            float4 w = *(const float4*)&W[(kb * 16 + kk) * HID + p4 * 4];
            *(float4*)&Ws[kk][p4 * 4] = w;
        }
        __syncthreads();
        #pragma unroll
        for (int kk = 0; kk < 16; kk++) {
            float4 af0 = *(const float4*)&Xs[kk][tr * 8];
            float4 af1 = *(const float4*)&Xs[kk][tr * 8 + 4];
            ull a[8];
            a[0] = pack2(af0.x); a[1] = pack2(af0.y);
            a[2] = pack2(af0.z); a[3] = pack2(af0.w);
            a[4] = pack2(af1.x); a[5] = pack2(af1.y);
            a[6] = pack2(af1.z); a[7] = pack2(af1.w);
            F4U b0, b1;
            b0.f = *(const float4*)&Ws[kk][tc * 8];
            b1.f = *(const float4*)&Ws[kk][tc * 8 + 4];
            ull b[4] = {b0.u[0], b0.u[1], b1.u[0], b1.u[1]};
            #pragma unroll
            for (int r = 0; r < 8; r++)
                #pragma unroll
                for (int c = 0; c < 4; c++) fma2(acc[r][c], a[r], b[c]);
        }
        __syncthreads();
    }
    #pragma unroll
    for (int r = 0; r < 8; r++) {
        int row = rowBase + tr * 8 + r;
        if (row < NN) {
            uint u[4];
            #pragma unroll
            for (int c = 0; c < 4; c++) {
                float2 f = *(float2*)&acc[r][c];
                u[c] = h2u(f.x, f.y);
            }
            *(uint4*)&g_xwh[row * 32 + tc * 4] = make_uint4(u[0], u[1], u[2], u[3]);
        }
    }
}

// ---------------- scale: xw' = dinv[row] * xw (in place, fp32 math) -------
__global__ void k_scale() {
    int tid = blockIdx.x * blockDim.x + threadIdx.x;   // NN*8
    if (tid >= NN * 8) return;
    int row = tid >> 3;
    float di = g_dinv[row];
    uint4 v = ((uint4*)g_xwh)[tid];
    float2 f;
    f = u2f(v.x); v.x = h2u(f.x * di, f.y * di);
    f = u2f(v.y); v.y = h2u(f.x * di, f.y * di);
    f = u2f(v.z); v.z = h2u(f.x * di, f.y * di);
    f = u2f(v.w); v.w = h2u(f.x * di, f.y * di);
    ((uint4*)g_xwh)[tid] = v;
}

// ---------------- gather1 FUSED with GEMM2 --------------------------------
// reads pre-scaled xw' (no per-edge dinv loads, no prefetch pipeline);
// h = relu(di*(Σ xw'[s] + xw'[i]) + b1) staged in smem fp32;
// hw' = fp16(di * (h @ W2)) written directly.
__global__ void __launch_bounds__(256) k_gather1f(const float* __restrict__ b1,
                                                  const float* __restrict__ W2) {
    __shared__ ull  W2p[64][21];     // col-pairs, padded
    __shared__ float h_sm[8][68];    // 8 warps x 64 floats (+pad)
    int t = threadIdx.x;
    #pragma unroll
    for (int q = 0; q < 5; q++) {
        int L = t + q * 256;          // 0..1279
        int k = L / 20, j = L - k * 20;
        W2p[k][j] = *(const ull*)&W2[k * 40 + j * 2];
    }
    __syncthreads();

    int warp = t >> 5, lane = t & 31;
    int i = blockIdx.x * 8 + warp;    // grid*8 == NN exactly
    int start = g_rowptr[i], end = g_rowptr[i + 1];
    int fl = lane & 7, es = lane >> 3;     // es 0..3
    const uint4* X = (const uint4*)g_xwh;  // row = 8 uint4
    float a[8], c[8];
    #pragma unroll
    for (int k = 0; k < 8; k++) { a[k] = 0.f; c[k] = 0.f; }
    for (int b = start + es; b < end; b += 8) {
        {
            int s = g_adjeid[b].x;
            uint4 v = X[s * 8 + fl];
            float2 f;
            f = u2f(v.x); a[0] += f.x; a[1] += f.y;
            f = u2f(v.y); a[2] += f.x; a[3] += f.y;
            f = u2f(v.z); a[4] += f.x; a[5] += f.y;
            f = u2f(v.w); a[6] += f.x; a[7] += f.y;
        }
        int b2 = b + 4;
        if (b2 < end) {
            int s = g_adjeid[b2].x;
            uint4 v = X[s * 8 + fl];
            float2 f;
            f = u2f(v.x); c[0] += f.x; c[1] += f.y;
            f = u2f(v.y); c[2] += f.x; c[3] += f.y;
            f = u2f(v.z); c[4] += f.x; c[5] += f.y;
            f = u2f(v.w); c[6] += f.x; c[7] += f.y;
        }
    }
    #pragma unroll
    for (int k = 0; k < 8; k++) a[k] += c[k];
    #pragma unroll
    for (int k = 0; k < 8; k++) a[k] += __shfl_down_sync(0xffffffffu, a[k], 16);
    #pragma unroll
    for (int k = 0; k < 8; k++) a[k] += __shfl_down_sync(0xffffffffu, a[k], 8);
    float di = g_dinv[i];
    if (lane < 8) {
        uint4 sv = X[i * 8 + fl];
        float sf[8];
        float2 f;
        f = u2f(sv.x); sf[0] = f.x; sf[1] = f.y;
        f = u2f(sv.y); sf[2] = f.x; sf[3] = f.y;
        f = u2f(sv.z); sf[4] = f.x; sf[5] = f.y;
        f = u2f(sv.w); sf[6] = f.x; sf[7] = f.y;
        float4 bb0 = ((const float4*)b1)[fl * 2];
        float4 bb1 = ((const float4*)b1)[fl * 2 + 1];
        float bbv[8] = {bb0.x, bb0.y, bb0.z, bb0.w, bb1.x, bb1.y, bb1.z, bb1.w};
        float* hrow = &h_sm[warp][fl * 8];
        #pragma unroll
        for (int k = 0; k < 8; k++)
            hrow[k] = fmaxf(di * (a[k] + sf[k]) + bbv[k], 0.f);
    }
    __syncwarp();
    // GEMM2 for this row: lanes 0..19 each produce one col-pair
    if (lane < 20) {
        ull acc = 0ULL;
        const float4* h4 = (const float4*)h_sm[warp];
        #pragma unroll
        for (int kq = 0; kq < 16; kq++) {
            float4 hv = h4[kq];
            fma2(acc, pack2(hv.x), W2p[kq*4+0][lane]);
            fma2(acc, pack2(hv.y), W2p[kq*4+1][lane]);
            fma2(acc, pack2(hv.z), W2p[kq*4+2][lane]);
            fma2(acc, pack2(hv.w), W2p[kq*4+3][lane]);
        }
        ull m = mul2(acc, pack2(di));
        float2 f = *(float2*)&m;
        ((uint*)g_hwh)[i * 20 + lane] = h2u(f.x, f.y);
    }
}

// ---------------- layer-2 gather fused with rowfinal ----------------------
__global__ void k_gather2f(const float* __restrict__ b2, float* __restrict__ out) {
    int warp = threadIdx.x >> 5, lane = threadIdx.x & 31;
    int i = blockIdx.x * 8 + warp;
    if (i >= NN) return;
    int start = g_rowptr[i], end = g_rowptr[i + 1];
    int es = lane / 10;
    int fl = lane - es * 10;
    bool act = (lane < 30);
    const uint2* H = (const uint2*)g_hwh;   // row = 10 uint2
    float4 a0 = make_float4(0.f,0.f,0.f,0.f), a1 = a0;
    if (act) {
        for (int b = start + es; b < end; b += 6) {
            {
                int s = g_adjeid[b].x;
                uint2 hv = H[s * 10 + fl];
                float2 f0 = u2f(hv.x), f1 = u2f(hv.y);
                a0.x += f0.x; a0.y += f0.y; a0.z += f1.x; a0.w += f1.y;
            }
            int b2i = b + 3;
            if (b2i < end) {
                int s = g_adjeid[b2i].x;
                uint2 hv = H[s * 10 + fl];
                float2 f0 = u2f(hv.x), f1 = u2f(hv.y);
                a1.x += f0.x; a1.y += f0.y; a1.z += f1.x; a1.w += f1.y;
            }
        }
    }
    a0.x += a1.x; a0.y += a1.y; a0.z += a1.z; a0.w += a1.w;
    a0.x += __shfl_down_sync(0xffffffffu, a0.x, 10) + __shfl_down_sync(0xffffffffu, a0.x, 20);
    a0.y += __shfl_down_sync(0xffffffffu, a0.y, 10) + __shfl_down_sync(0xffffffffu, a0.y, 20);
    a0.z += __shfl_down_sync(0xffffffffu, a0.z, 10) + __shfl_down_sync(0xffffffffu, a0.z, 20);
    a0.w += __shfl_down_sync(0xffffffffu, a0.w, 10) + __shfl_down_sync(0xffffffffu, a0.w, 20);

    const float NEG = -1e30f;
    float4 v = make_float4(NEG, NEG, NEG, NEG);
    if (lane < 10) {
        uint2 sv = H[i * 10 + fl];
        float2 s0 = u2f(sv.x), s1 = u2f(sv.y);
        float di = g_dinv[i];
        float4 bb = ((const float4*)b2)[fl];
        v.x = di * (a0.x + s0.x) + bb.x;
        v.y = di * (a0.y + s0.y) + bb.y;
        v.z = di * (a0.z + s1.x) + bb.z;
        v.w = di * (a0.w + s1.y) + bb.w;
    }
    float m = fmaxf(fmaxf(v.x, v.y), fmaxf(v.z, v.w));
    #pragma unroll
    for (int o = 16; o > 0; o >>= 1) m = fmaxf(m, __shfl_xor_sync(0xffffffffu, m, o));
    float4 ev = make_float4(0.f, 0.f, 0.f, 0.f);
    float s = 0.f, ss = 0.f;
    if (lane < 10) {
        ev.x = __expf(v.x - m); ev.y = __expf(v.y - m);
        ev.z = __expf(v.z - m); ev.w = __expf(v.w - m);
        s  = ev.x + ev.y + ev.z + ev.w;
        ss = v.x*v.x + v.y*v.y + v.z*v.z + v.w*v.w;
    }
    #pragma unroll
    for (int o = 16; o > 0; o >>= 1) {
        s  += __shfl_xor_sync(0xffffffffu, s, o);
        ss += __shfl_xor_sync(0xffffffffu, ss, o);
    }
    if (lane < 10) {
        float lse = m + logf(s);
        float inv_s = 1.0f / s;
        float rn = 1.0f / fmaxf(sqrtf(ss), 1e-8f);
        int idx = i * 10 + fl;
        ((float4*)(out + OFF_XOUT))[idx] = v;
        ((float4*)(out + OFF_LOGSM))[idx] = make_float4(v.x - lse, v.y - lse, v.z - lse, v.w - lse);
        ((float4*)(out + OFF_SM))[idx] = make_float4(ev.x * inv_s, ev.y * inv_s, ev.z * inv_s, ev.w * inv_s);
        ((float4*)g_xn)[idx] = make_float4(v.x * rn, v.y * rn, v.z * rn, v.w * rn);
    }
}

// ---------------- per-edge cosine via CSR (d-row register reuse, fp32) ----
__global__ void k_edge(float* __restrict__ out) {
    int warp = threadIdx.x >> 5, lane = threadIdx.x & 31;
    int row = blockIdx.x * 8 + warp;
    if (row >= NN) return;
    int start = g_rowptr[row], end = g_rowptr[row + 1];
    const float4* XN = (const float4*)g_xn;   // row = 10 float4
    float4 nd[10];
    #pragma unroll
    for (int j = 0; j < 10; j++) nd[j] = XN[row * 10 + j];
    for (int slot = start + lane; slot < end; slot += 32) {
        int2 ae = g_adjeid[slot];
        int s = ae.x;
        float d0 = 0.f, d1 = 0.f, d2 = 0.f, d3 = 0.f;
        #pragma unroll
        for (int j = 0; j < 10; j += 2) {
            float4 a = XN[s * 10 + j];
            float4 b = XN[s * 10 + j + 1];
            d0 += a.x * nd[j].x + a.y * nd[j].y;
            d1 += a.z * nd[j].z + a.w * nd[j].w;
            d2 += b.x * nd[j+1].x + b.y * nd[j+1].y;
            d3 += b.z * nd[j+1].z + b.w * nd[j+1].w;
        }
        out[OFF_COS + ae.y] = 1.0f - (d0 + d1 + d2 + d3);
    }
}

// ---------------- launch ----------------
extern "C" void kernel_launch(void* const* d_in, const int* in_sizes, int n_in,
                              void* d_out, int out_size) {
    const float* x   = (const float*)d_in[0];
    const void*  ei  = d_in[1];
    const float* ew  = (const float*)d_in[2];
    const float* W1  = (const float*)d_in[3];
    const float* b1  = (const float*)d_in[4];
    const float* W2  = (const float*)d_in[5];
    const float* b2  = (const float*)d_in[6];
    float* out = (float*)d_out;

    const int TB = 256;

    static cudaStream_t s2 = nullptr;
    static cudaEvent_t ev0 = nullptr, evS = nullptr, ev1 = nullptr;
    static void* p_degi = nullptr;
    if (!s2) {
        cudaStreamCreateWithFlags(&s2, cudaStreamNonBlocking);
        cudaEventCreateWithFlags(&ev0, cudaEventDisableTiming);
        cudaEventCreateWithFlags(&evS, cudaEventDisableTiming);
        cudaEventCreateWithFlags(&ev1, cudaEventDisableTiming);
        cudaGetSymbolAddress(&p_degi, g_degi);
    }

    // fork point for the independent GEMM1 branch (executes from t=0)
    cudaEventRecord(ev0, 0);
    cudaStreamWaitEvent(s2, ev0, 0);

    // edge-structure chain
    cudaMemsetAsync(p_degi, 0, NN * sizeof(int), 0);
    k_convert<<<(EE + TB - 1) / TB, TB>>>(ei, ew, out);
    k_scan<<<SNB, SCAN_T>>>();
    cudaEventRecord(evS, 0);
    k_fill<<<(EE + TB - 1) / TB, TB>>>(ei);

    // side stream: gemm1 from t=0, then dinv pre-scale (needs scan)
    k_gemm1<<<(NN + G1_ROWS - 1) / G1_ROWS, 128, 0, s2>>>(x, W1);
    cudaStreamWaitEvent(s2, evS, 0);
    k_scale<<<(NN * 8 + TB - 1) / TB, TB, 0, s2>>>();
    cudaEventRecord(ev1, s2);
    cudaStreamWaitEvent(0, ev1, 0);

    // join: fused gather1+gemm2 (pre-scaled xw), then tail
    k_gather1f<<<NN / 8, 256>>>(b1, W2);
    k_gather2f<<<(NN + 7) / 8, 256>>>(b2, out);
    k_edge<<<(NN + 7) / 8, 256>>>(out);
}